// round 1
// baseline (speedup 1.0000x reference)
#include <cuda_runtime.h>
#include <math.h>
#include <stdint.h>

#define BATCH 25
#define SEQT  600
#define EMBD  300
#define HID   512
#define G3    1536              // 3*HID
#define MROWS (BATCH*SEQT)      // 15000

// ---------------- scratch (device globals; no allocation allowed) ----------
__device__ float g_xg[(size_t)MROWS * G3];   // 92.16 MB, reused for xg0 then xg1
__device__ float g_out0[(size_t)MROWS * HID];// 30.72 MB  (layer-0 outputs, all t)
__device__ float g_hbuf0[BATCH * HID];
__device__ float g_hbuf1[BATCH * HID];
__device__ float g_h0f[BATCH * HID];
__device__ float g_h1f[BATCH * HID];
__device__ unsigned g_ctr;

// ---------------- reset barrier counter (stream-ordered; no spinners alive)
__global__ void reset_kernel() {
    if (threadIdx.x == 0) g_ctr = 0u;
}

// ---------------- fp32 GEMM: g_xg[M x 1536] = A[M x K] @ W[1536 x K]^T + bias
// words != null  -> A row r = emb[words[r]] (embedding gather), K = 300
// words == null  -> A = g_out0, K = 512
__global__ __launch_bounds__(256) void gemm_kernel(
    const int*   __restrict__ words,
    const float* __restrict__ emb,
    const float* __restrict__ Wt,     // [1536][K]
    const float* __restrict__ bias,   // [1536]
    int K)
{
    __shared__ float As[8][132];
    __shared__ float Ws[8][132];

    const int tid  = threadIdx.x;
    const int tx   = tid & 15;
    const int ty   = tid >> 4;
    const int row0 = blockIdx.y * 128;
    const int col0 = blockIdx.x * 128;

    float acc[8][8];
#pragma unroll
    for (int i = 0; i < 8; i++)
#pragma unroll
        for (int j = 0; j < 8; j++) acc[i][j] = 0.f;

    const int lr  = tid >> 1;          // 0..127
    const int lkq = (tid & 1) * 4;     // 0 or 4
    const int grow = row0 + lr;

    const float* arow = nullptr;
    if (grow < MROWS)
        arow = words ? (emb + (size_t)words[grow] * K)
                     : (g_out0 + (size_t)grow * K);
    const float* wrow = Wt + (size_t)(col0 + lr) * K;

    for (int k0 = 0; k0 < K; k0 += 8) {
        const int gk = k0 + lkq;
        // A tile (gathered or direct), zero-padded at edges
        float4 va = make_float4(0.f, 0.f, 0.f, 0.f);
        if (arow) {
            if (gk + 3 < K) {
                va = *(const float4*)(arow + gk);
            } else {
                if (gk + 0 < K) va.x = arow[gk + 0];
                if (gk + 1 < K) va.y = arow[gk + 1];
                if (gk + 2 < K) va.z = arow[gk + 2];
                if (gk + 3 < K) va.w = arow[gk + 3];
            }
        }
        As[lkq + 0][lr] = va.x; As[lkq + 1][lr] = va.y;
        As[lkq + 2][lr] = va.z; As[lkq + 3][lr] = va.w;

        // W tile
        float4 vw = make_float4(0.f, 0.f, 0.f, 0.f);
        if (gk + 3 < K) {
            vw = *(const float4*)(wrow + gk);
        } else {
            if (gk + 0 < K) vw.x = wrow[gk + 0];
            if (gk + 1 < K) vw.y = wrow[gk + 1];
            if (gk + 2 < K) vw.z = wrow[gk + 2];
            if (gk + 3 < K) vw.w = wrow[gk + 3];
        }
        Ws[lkq + 0][lr] = vw.x; Ws[lkq + 1][lr] = vw.y;
        Ws[lkq + 2][lr] = vw.z; Ws[lkq + 3][lr] = vw.w;

        __syncthreads();
#pragma unroll
        for (int kk = 0; kk < 8; kk++) {
            float a[8], b[8];
            float4 a0 = *(const float4*)&As[kk][ty * 8];
            float4 a1 = *(const float4*)&As[kk][ty * 8 + 4];
            float4 b0 = *(const float4*)&Ws[kk][tx * 8];
            float4 b1 = *(const float4*)&Ws[kk][tx * 8 + 4];
            a[0]=a0.x; a[1]=a0.y; a[2]=a0.z; a[3]=a0.w;
            a[4]=a1.x; a[5]=a1.y; a[6]=a1.z; a[7]=a1.w;
            b[0]=b0.x; b[1]=b0.y; b[2]=b0.z; b[3]=b0.w;
            b[4]=b1.x; b[5]=b1.y; b[6]=b1.z; b[7]=b1.w;
#pragma unroll
            for (int i = 0; i < 8; i++)
#pragma unroll
                for (int j = 0; j < 8; j++)
                    acc[i][j] = fmaf(a[i], b[j], acc[i][j]);
        }
        __syncthreads();
    }

#pragma unroll
    for (int i = 0; i < 8; i++) {
        const int gr = row0 + ty * 8 + i;
        if (gr >= MROWS) continue;
        float* crow = g_xg + (size_t)gr * G3 + col0 + tx * 8;
        const float* brow = bias + col0 + tx * 8;
#pragma unroll
        for (int j = 0; j < 8; j++)
            crow[j] = acc[i][j] + brow[j];
    }
}

// ---------------- persistent GRU layer: 128 blocks, 4 hidden units each -----
// Per step: gh = h @ w_hh^T (block's 12 rows), elementwise gates, grid barrier.
__global__ __launch_bounds__(256, 1) void gru_layer_kernel(
    const float* __restrict__ w_hh,   // [1536][512]
    const float* __restrict__ b_hh,   // [1536]
    const float* __restrict__ h_init, // [25][512]
    int layer)
{
    extern __shared__ float smem[];
    float* hs  = smem;                 // [25][516] staged h
    float* ws  = hs + 25 * 516;        // [12][516] block's w_hh rows (persistent)
    float* ps  = ws + 12 * 516;        // [8][12][32] warp partials
    float* bhs = ps + 8 * 12 * 32;     // [12] biases

    const int tid  = threadIdx.x;
    const int wid  = tid >> 5;
    const int lane = tid & 31;
    const int u0   = blockIdx.x * 4;

    float* outp = (layer == 0) ? g_out0 : nullptr;
    float* hfin = (layer == 0) ? g_h0f : g_h1f;

    // load this block's 12 w_hh rows (rows: g*512 + u0 + uu) once
    for (int i = tid; i < 12 * 128; i += blockDim.x) {
        const int j  = i >> 7;                 // local row 0..11
        const int kq = (i & 127) << 2;         // k 0..508 step 4
        const int grow = (j >> 2) * HID + u0 + (j & 3);
        float4 v = *(const float4*)(w_hh + (size_t)grow * HID + kq);
        float* dst = ws + j * 516 + kq;
        dst[0] = v.x; dst[1] = v.y; dst[2] = v.z; dst[3] = v.w;
    }
    if (tid < 12) bhs[tid] = b_hh[(tid >> 2) * HID + u0 + (tid & 3)];

    for (int t = 0; t < SEQT; t++) {
        const float* hsrc = (t == 0) ? h_init : ((t & 1) ? g_hbuf0 : g_hbuf1);
        float*       wdst = (t & 1) ? g_hbuf1 : g_hbuf0;

        __syncthreads();  // ws ready (t=0) / previous-step smem consumers done

        // stage h into smem; __ldcg: h written by OTHER SMs -> bypass stale L1
        const float4* s4 = (const float4*)hsrc;
        for (int i = tid; i < (BATCH * HID) / 4; i += blockDim.x) {
            float4 v = __ldcg(s4 + i);
            const int b  = i >> 7;
            const int kq = (i & 127) << 2;
            float* dst = hs + b * 516 + kq;
            dst[0] = v.x; dst[1] = v.y; dst[2] = v.z; dst[3] = v.w;
        }
        __syncthreads();

        // gh partials: warp 'wid' covers k in [wid*64, wid*64+64); lane <-> batch
        if (lane < BATCH) {
            float acc[12];
#pragma unroll
            for (int j = 0; j < 12; j++) acc[j] = 0.f;
            const float* hrow = hs + lane * 516;
            const int kbeg = wid * 64;
#pragma unroll 4
            for (int kq = kbeg; kq < kbeg + 64; kq += 4) {
                float4 hv = *(const float4*)(hrow + kq);
#pragma unroll
                for (int j = 0; j < 12; j++) {
                    float4 wv = *(const float4*)(ws + j * 516 + kq);
                    acc[j] = fmaf(hv.x, wv.x, acc[j]);
                    acc[j] = fmaf(hv.y, wv.y, acc[j]);
                    acc[j] = fmaf(hv.z, wv.z, acc[j]);
                    acc[j] = fmaf(hv.w, wv.w, acc[j]);
                }
            }
#pragma unroll
            for (int j = 0; j < 12; j++)
                ps[(wid * 12 + j) * 32 + lane] = acc[j];
        }
        __syncthreads();

        // reduce over 8 warps + gate nonlinearity + h update (100 threads)
        if (tid < 100) {
            const int b  = tid >> 2;
            const int uu = tid & 3;
            const int u  = u0 + uu;
            float gr_ = bhs[uu], gz_ = bhs[4 + uu], gn_ = bhs[8 + uu];
#pragma unroll
            for (int w = 0; w < 8; w++) {
                gr_ += ps[(w * 12 + uu    ) * 32 + b];
                gz_ += ps[(w * 12 + 4 + uu) * 32 + b];
                gn_ += ps[(w * 12 + 8 + uu) * 32 + b];
            }
            const float* xrow = g_xg + ((size_t)b * SEQT + t) * G3;
            const float xr = xrow[u], xz = xrow[HID + u], xn = xrow[2 * HID + u];
            const float r = 1.f / (1.f + expf(-(xr + gr_)));
            const float z = 1.f / (1.f + expf(-(xz + gz_)));
            const float n = tanhf(xn + r * gn_);
            const float hold = hs[b * 516 + u];
            const float hn = (1.f - z) * n + z * hold;
            wdst[b * HID + u] = hn;
            if (outp) outp[((size_t)b * SEQT + t) * HID + u] = hn;
            if (t == SEQT - 1) hfin[b * HID + u] = hn;
        }

        // grid barrier (monotonic counter, reset by reset_kernel pre-launch)
        __threadfence();
        __syncthreads();
        if (t < SEQT - 1) {
            if (tid == 0) {
                atomicAdd(&g_ctr, 1u);
                const unsigned target = (unsigned)(t + 1) * gridDim.x;
                while (*((volatile unsigned*)&g_ctr) < target) { }
                __threadfence();
            }
            __syncthreads();
        }
    }
}

// ---------------- finalize: sig = sigmoid(h1_final . fc_w + fc_b); pack out --
__global__ void finalize_kernel(const float* __restrict__ fc_w,
                                const float* __restrict__ fc_b,
                                float* __restrict__ out)
{
    if (blockIdx.x < 100) {
        const int idx = blockIdx.x * 256 + threadIdx.x;     // 0..25599
        const float v = (idx < BATCH * HID) ? g_h0f[idx]
                                            : g_h1f[idx - BATCH * HID];
        out[25 + idx] = v;
    } else {
        const int b = threadIdx.x;
        if (b < BATCH) {
            float s = fc_b[0];
            for (int k = 0; k < HID; k++)
                s += g_h1f[b * HID + k] * fc_w[k];
            out[b] = 1.f / (1.f + expf(-s));
        }
    }
}

// ---------------- launch ----------------------------------------------------
extern "C" void kernel_launch(void* const* d_in, const int* in_sizes, int n_in,
                              void* d_out, int out_size)
{
    const int*   words  = (const int*)  d_in[0];
    const float* hidden = (const float*)d_in[1];
    const float* emb    = (const float*)d_in[2];
    const float* w_ih0  = (const float*)d_in[3];
    const float* w_hh0  = (const float*)d_in[4];
    const float* b_ih0  = (const float*)d_in[5];
    const float* b_hh0  = (const float*)d_in[6];
    const float* w_ih1  = (const float*)d_in[7];
    const float* w_hh1  = (const float*)d_in[8];
    const float* b_ih1  = (const float*)d_in[9];
    const float* b_hh1  = (const float*)d_in[10];
    const float* fc_w   = (const float*)d_in[11];
    const float* fc_b   = (const float*)d_in[12];
    float* out = (float*)d_out;

    const int smem_bytes = (25 * 516 + 12 * 516 + 8 * 12 * 32 + 16) * 4;
    cudaFuncSetAttribute(gru_layer_kernel,
                         cudaFuncAttributeMaxDynamicSharedMemorySize, smem_bytes);

    const dim3 ggrid(G3 / 128, (MROWS + 127) / 128);

    // layer 0: xg0 (embedding gather fused), then recurrence (writes out0, h0f)
    gemm_kernel<<<ggrid, 256>>>(words, emb, w_ih0, b_ih0, EMBD);
    reset_kernel<<<1, 32>>>();
    gru_layer_kernel<<<128, 256, smem_bytes>>>(w_hh0, b_hh0, hidden, 0);

    // layer 1: xg1 from out0 (reuses g_xg), then recurrence (writes h1f)
    gemm_kernel<<<ggrid, 256>>>(nullptr, nullptr, w_ih1, b_ih1, HID);
    reset_kernel<<<1, 32>>>();
    gru_layer_kernel<<<128, 256, smem_bytes>>>(w_hh1, b_hh1, hidden + BATCH * HID, 1);

    finalize_kernel<<<101, 256>>>(fc_w, fc_b, out);
}

// round 2
// speedup vs baseline: 1.3129x; 1.3129x over previous
#include <cuda_runtime.h>
#include <math.h>
#include <stdint.h>

#define BATCH 25
#define SEQT  600
#define EMBD  300
#define HID   512
#define G3    1536              // 3*HID
#define MROWS (BATCH*SEQT)      // 15000

// ---------------- scratch (device globals; no allocation allowed) ----------
__device__ float g_xg[(size_t)MROWS * G3];   // 92.16 MB, reused for xg0 then xg1
__device__ float g_out0[(size_t)MROWS * HID];// 30.72 MB  (layer-0 outputs, all t)
__device__ float g_hbuf0[BATCH * HID];
__device__ float g_hbuf1[BATCH * HID];
__device__ float g_h0f[BATCH * HID];
__device__ float g_h1f[BATCH * HID];
__device__ unsigned g_ctr;

// ---------------- release/acquire grid-barrier primitives -------------------
__device__ __forceinline__ void red_release_add(unsigned* p, unsigned v) {
    asm volatile("red.release.gpu.global.add.u32 [%0], %1;"
                 :: "l"(p), "r"(v) : "memory");
}
__device__ __forceinline__ unsigned ld_acquire(unsigned* p) {
    unsigned v;
    asm volatile("ld.acquire.gpu.global.u32 %0, [%1];"
                 : "=r"(v) : "l"(p) : "memory");
    return v;
}

// ---------------- reset barrier counter (stream-ordered; no spinners alive)
__global__ void reset_kernel() {
    if (threadIdx.x == 0) g_ctr = 0u;
}

// ---------------- fp32 GEMM (double-buffered):
// g_xg[M x 1536] = A[M x K] @ W[1536 x K]^T + bias
// words != null  -> A row r = emb[words[r]] (embedding gather), K = 300
// words == null  -> A = g_out0, K = 512
__global__ __launch_bounds__(256) void gemm_kernel(
    const int*   __restrict__ words,
    const float* __restrict__ emb,
    const float* __restrict__ Wt,     // [1536][K]
    const float* __restrict__ bias,   // [1536]
    int K)
{
    __shared__ float As[2][8][132];
    __shared__ float Ws[2][8][132];

    const int tid  = threadIdx.x;
    const int tx   = tid & 15;
    const int ty   = tid >> 4;
    const int row0 = blockIdx.y * 128;
    const int col0 = blockIdx.x * 128;

    float acc[8][8];
#pragma unroll
    for (int i = 0; i < 8; i++)
#pragma unroll
        for (int j = 0; j < 8; j++) acc[i][j] = 0.f;

    const int lr  = tid >> 1;          // 0..127
    const int lkq = (tid & 1) * 4;     // 0 or 4
    const int grow = row0 + lr;

    const float* arow = nullptr;
    if (grow < MROWS)
        arow = words ? (emb + (size_t)words[grow] * K)
                     : (g_out0 + (size_t)grow * K);
    const float* wrow = Wt + (size_t)(col0 + lr) * K;

    const int nt = (K + 7) / 8;

    // guarded vector loads
    auto loadA = [&](int gk) -> float4 {
        float4 v = make_float4(0.f, 0.f, 0.f, 0.f);
        if (arow) {
            if (gk + 3 < K) v = *(const float4*)(arow + gk);
            else {
                if (gk + 0 < K) v.x = arow[gk + 0];
                if (gk + 1 < K) v.y = arow[gk + 1];
                if (gk + 2 < K) v.z = arow[gk + 2];
                if (gk + 3 < K) v.w = arow[gk + 3];
            }
        }
        return v;
    };
    auto loadW = [&](int gk) -> float4 {
        float4 v = make_float4(0.f, 0.f, 0.f, 0.f);
        if (gk + 3 < K) v = *(const float4*)(wrow + gk);
        else {
            if (gk + 0 < K) v.x = wrow[gk + 0];
            if (gk + 1 < K) v.y = wrow[gk + 1];
            if (gk + 2 < K) v.z = wrow[gk + 2];
            if (gk + 3 < K) v.w = wrow[gk + 3];
        }
        return v;
    };

    // prologue: tile 0 into buffer 0
    {
        float4 va = loadA(lkq);
        float4 vw = loadW(lkq);
        As[0][lkq + 0][lr] = va.x; As[0][lkq + 1][lr] = va.y;
        As[0][lkq + 2][lr] = va.z; As[0][lkq + 3][lr] = va.w;
        Ws[0][lkq + 0][lr] = vw.x; Ws[0][lkq + 1][lr] = vw.y;
        Ws[0][lkq + 2][lr] = vw.z; Ws[0][lkq + 3][lr] = vw.w;
    }
    __syncthreads();

    for (int it = 0; it < nt; it++) {
        const int buf  = it & 1;
        const int nbuf = buf ^ 1;
        const bool have = (it + 1) < nt;

        float4 va2, vw2;
        if (have) {                       // issue global loads early
            va2 = loadA((it + 1) * 8 + lkq);
            vw2 = loadW((it + 1) * 8 + lkq);
        }

#pragma unroll
        for (int kk = 0; kk < 8; kk++) {
            float a[8], b[8];
            float4 a0 = *(const float4*)&As[buf][kk][ty * 8];
            float4 a1 = *(const float4*)&As[buf][kk][ty * 8 + 4];
            float4 b0 = *(const float4*)&Ws[buf][kk][tx * 8];
            float4 b1 = *(const float4*)&Ws[buf][kk][tx * 8 + 4];
            a[0]=a0.x; a[1]=a0.y; a[2]=a0.z; a[3]=a0.w;
            a[4]=a1.x; a[5]=a1.y; a[6]=a1.z; a[7]=a1.w;
            b[0]=b0.x; b[1]=b0.y; b[2]=b0.z; b[3]=b0.w;
            b[4]=b1.x; b[5]=b1.y; b[6]=b1.z; b[7]=b1.w;
#pragma unroll
            for (int i = 0; i < 8; i++)
#pragma unroll
                for (int j = 0; j < 8; j++)
                    acc[i][j] = fmaf(a[i], b[j], acc[i][j]);
        }

        if (have) {
            As[nbuf][lkq + 0][lr] = va2.x; As[nbuf][lkq + 1][lr] = va2.y;
            As[nbuf][lkq + 2][lr] = va2.z; As[nbuf][lkq + 3][lr] = va2.w;
            Ws[nbuf][lkq + 0][lr] = vw2.x; Ws[nbuf][lkq + 1][lr] = vw2.y;
            Ws[nbuf][lkq + 2][lr] = vw2.z; Ws[nbuf][lkq + 3][lr] = vw2.w;
        }
        __syncthreads();
    }

#pragma unroll
    for (int i = 0; i < 8; i++) {
        const int gr = row0 + ty * 8 + i;
        if (gr >= MROWS) continue;
        float* crow = g_xg + (size_t)gr * G3 + col0 + tx * 8;
        const float* brow = bias + col0 + tx * 8;
#pragma unroll
        for (int j = 0; j < 8; j++)
            crow[j] = acc[i][j] + brow[j];
    }
}

// ---------------- persistent GRU layer: 128 blocks, 4 hidden units each -----
// Per step: warp-local h staging -> gh = h @ w_hh^T (block's 12 rows) ->
// partial reduce -> gates (with prefetched xg / h_old) -> release/acquire
// grid barrier.
__global__ __launch_bounds__(256, 1) void gru_layer_kernel(
    const float* __restrict__ w_hh,   // [1536][512]
    const float* __restrict__ b_hh,   // [1536]
    const float* __restrict__ h_init, // [25][512]
    int layer)
{
    __shared__ float hs[25 * 516];     // staged h; warp w owns k-slice [w*64,w*64+64)
    __shared__ float ws[12 * 516];     // block's 12 w_hh rows (persistent)
    __shared__ float ps[8 * 12 * 32];  // warp partials
    __shared__ float bhs[12];

    const int tid  = threadIdx.x;
    const int wid  = tid >> 5;
    const int lane = tid & 31;
    const int u0   = blockIdx.x * 4;
    const int kbeg = wid * 64;

    float* outp = (layer == 0) ? g_out0 : nullptr;
    float* hfin = (layer == 0) ? g_h0f : g_h1f;

    // load this block's 12 w_hh rows (rows: g*512 + u0 + uu) once
    for (int i = tid; i < 12 * 128; i += blockDim.x) {
        const int j  = i >> 7;                 // local row 0..11
        const int kq = (i & 127) << 2;         // k 0..508 step 4
        const int grow = (j >> 2) * HID + u0 + (j & 3);
        float4 v = *(const float4*)(w_hh + (size_t)grow * HID + kq);
        float* dst = ws + j * 516 + kq;
        dst[0] = v.x; dst[1] = v.y; dst[2] = v.z; dst[3] = v.w;
    }
    if (tid < 12) bhs[tid] = b_hh[(tid >> 2) * HID + u0 + (tid & 3)];
    __syncthreads();

    // per-thread gate identity (tid < 100)
    const int gb = tid >> 2;          // batch 0..24
    const int gu = tid & 3;           // local unit
    const int u  = u0 + gu;

    for (int t = 0; t < SEQT; t++) {
        const float* hsrc = (t == 0) ? h_init : ((t & 1) ? g_hbuf0 : g_hbuf1);
        float*       wdst = (t & 1) ? g_hbuf1 : g_hbuf0;

        // --- prefetch xg[t] and h_old into registers (off the critical tail)
        float xr = 0.f, xz = 0.f, xn = 0.f, hold = 0.f;
        if (tid < 100) {
            const float* xrow = g_xg + ((size_t)gb * SEQT + t) * G3;
            xr   = __ldcg(xrow + u);
            xz   = __ldcg(xrow + HID + u);
            xn   = __ldcg(xrow + 2 * HID + u);
            hold = __ldcg(hsrc + gb * HID + u);
        }

        // --- warp-local h staging: warp wid stages its own 64-wide k-slice
        {
            const float4* s4 = (const float4*)hsrc;      // [25][128] quads
            const int qbeg = kbeg >> 2;                  // quad offset of slice
#pragma unroll
            for (int i = lane; i < 400; i += 32) {       // 25 b x 16 quads
                const int b = i >> 4;
                const int q = i & 15;
                float4 v = __ldcg(s4 + b * 128 + qbeg + q);
                float* dst = hs + b * 516 + kbeg + q * 4;
                dst[0] = v.x; dst[1] = v.y; dst[2] = v.z; dst[3] = v.w;
            }
        }
        __syncwarp();

        // --- gh partials over this warp's k-slice; lane <-> batch
        if (lane < BATCH) {
            float acc[12];
#pragma unroll
            for (int j = 0; j < 12; j++) acc[j] = 0.f;
            const float* hrow = hs + lane * 516;
#pragma unroll 4
            for (int kq = kbeg; kq < kbeg + 64; kq += 4) {
                float4 hv = *(const float4*)(hrow + kq);
#pragma unroll
                for (int j = 0; j < 12; j++) {
                    float4 wv = *(const float4*)(ws + j * 516 + kq);
                    acc[j] = fmaf(hv.x, wv.x, acc[j]);
                    acc[j] = fmaf(hv.y, wv.y, acc[j]);
                    acc[j] = fmaf(hv.z, wv.z, acc[j]);
                    acc[j] = fmaf(hv.w, wv.w, acc[j]);
                }
            }
#pragma unroll
            for (int j = 0; j < 12; j++)
                ps[(wid * 12 + j) * 32 + lane] = acc[j];
        }
        __syncthreads();

        // --- reduce over 8 warps + gates + h update (100 threads)
        if (tid < 100) {
            float gr_ = bhs[gu], gz_ = bhs[4 + gu], gn_ = bhs[8 + gu];
#pragma unroll
            for (int w = 0; w < 8; w++) {
                gr_ += ps[(w * 12 + gu    ) * 32 + gb];
                gz_ += ps[(w * 12 + 4 + gu) * 32 + gb];
                gn_ += ps[(w * 12 + 8 + gu) * 32 + gb];
            }
            const float r = 1.f / (1.f + expf(-(xr + gr_)));
            const float z = 1.f / (1.f + expf(-(xz + gz_)));
            const float n = tanhf(xn + r * gn_);
            const float hn = (1.f - z) * n + z * hold;
            wdst[gb * HID + u] = hn;
            if (outp) outp[((size_t)gb * SEQT + t) * HID + u] = hn;
            if (t == SEQT - 1) hfin[gb * HID + u] = hn;
        }
        __syncthreads();

        // --- grid barrier (release arrive / acquire spin)
        if (t < SEQT - 1) {
            if (tid == 0) {
                red_release_add(&g_ctr, 1u);
                const unsigned target = (unsigned)(t + 1) * gridDim.x;
                while (ld_acquire(&g_ctr) < target) { }
            }
            __syncthreads();
        }
    }
}

// ---------------- finalize: sig = sigmoid(h1_final . fc_w + fc_b); pack out --
__global__ void finalize_kernel(const float* __restrict__ fc_w,
                                const float* __restrict__ fc_b,
                                float* __restrict__ out)
{
    if (blockIdx.x < 100) {
        const int idx = blockIdx.x * 256 + threadIdx.x;     // 0..25599
        const float v = (idx < BATCH * HID) ? g_h0f[idx]
                                            : g_h1f[idx - BATCH * HID];
        out[25 + idx] = v;
    } else {
        const int b = threadIdx.x;
        if (b < BATCH) {
            float s = fc_b[0];
            for (int k = 0; k < HID; k++)
                s += g_h1f[b * HID + k] * fc_w[k];
            out[b] = 1.f / (1.f + expf(-s));
        }
    }
}

// ---------------- launch ----------------------------------------------------
extern "C" void kernel_launch(void* const* d_in, const int* in_sizes, int n_in,
                              void* d_out, int out_size)
{
    const int*   words  = (const int*)  d_in[0];
    const float* hidden = (const float*)d_in[1];
    const float* emb    = (const float*)d_in[2];
    const float* w_ih0  = (const float*)d_in[3];
    const float* w_hh0  = (const float*)d_in[4];
    const float* b_ih0  = (const float*)d_in[5];
    const float* b_hh0  = (const float*)d_in[6];
    const float* w_ih1  = (const float*)d_in[7];
    const float* w_hh1  = (const float*)d_in[8];
    const float* b_ih1  = (const float*)d_in[9];
    const float* b_hh1  = (const float*)d_in[10];
    const float* fc_w   = (const float*)d_in[11];
    const float* fc_b   = (const float*)d_in[12];
    float* out = (float*)d_out;

    const dim3 ggrid(G3 / 128, (MROWS + 127) / 128);

    // layer 0: xg0 (embedding gather fused), then recurrence (writes out0, h0f)
    gemm_kernel<<<ggrid, 256>>>(words, emb, w_ih0, b_ih0, EMBD);
    reset_kernel<<<1, 32>>>();
    gru_layer_kernel<<<128, 256>>>(w_hh0, b_hh0, hidden, 0);

    // layer 1: xg1 from out0 (reuses g_xg), then recurrence (writes h1f)
    gemm_kernel<<<ggrid, 256>>>(nullptr, nullptr, w_ih1, b_ih1, HID);
    reset_kernel<<<1, 32>>>();
    gru_layer_kernel<<<128, 256>>>(w_hh1, b_hh1, hidden + BATCH * HID, 1);

    finalize_kernel<<<101, 256>>>(fc_w, fc_b, out);
}